// round 10
// baseline (speedup 1.0000x reference)
#include <cuda_runtime.h>
#include <cstdint>
#include <math.h>
#include <math_constants.h>

#define NCTA     128
#define NTHREADS 256
#define HDIM     512
#define TSTEPS   31
#define BSEQ     512
#define OUTC     12

typedef unsigned long long ull;

// ---------------- device globals (scratch) ----------------
__device__ float g_h0[(BSEQ + 1) * HDIM];
__device__ float g_h1[(BSEQ + 1) * HDIM];
__device__ float g_scale[HDIM];
__device__ float g_shift[HDIM];
// per-CTA flag barrier: 2 phase slots x 128 CTAs
__device__ unsigned g_flags[2 * NCTA];

__device__ __forceinline__ void st_relaxed_gpu(unsigned* p, unsigned v) {
    asm volatile("st.relaxed.gpu.u32 [%0], %1;" :: "l"(p), "r"(v) : "memory");
}
__device__ __forceinline__ uint4 ld_vol_v4(const uint4* p) {
    uint4 v;
    asm volatile("ld.volatile.global.v4.u32 {%0,%1,%2,%3}, [%4];"
                 : "=r"(v.x), "=r"(v.y), "=r"(v.z), "=r"(v.w) : "l"(p) : "memory");
    return v;
}
__device__ __forceinline__ void fence_gpu() {
    asm volatile("fence.acq_rel.gpu;" ::: "memory");
}
__device__ __forceinline__ void st_release_cta(unsigned* p, unsigned v) {
    asm volatile("st.release.cta.shared::cta.u32 [%0], %1;"
                 :: "r"((unsigned)__cvta_generic_to_shared(p)), "r"(v) : "memory");
}
__device__ __forceinline__ unsigned ld_acquire_cta(const unsigned* p) {
    unsigned v;
    asm volatile("ld.acquire.cta.shared::cta.u32 %0, [%1];"
                 : "=r"(v) : "r"((unsigned)__cvta_generic_to_shared((void*)p)) : "memory");
    return v;
}

// fast activations (rel err ~1e-6)
__device__ __forceinline__ float sigm_f(float x) { return __fdividef(1.0f, 1.0f + __expf(-x)); }
__device__ __forceinline__ float tanh_f(float x) { return 1.0f - __fdividef(2.0f, __expf(2.0f * x) + 1.0f); }

// packed fp32x2 (sm_103a FFMA2 via PTX)
__device__ __forceinline__ ull pk(float x, float y) {
    ull r; asm("mov.b64 %0, {%1, %2};" : "=l"(r) : "f"(x), "f"(y)); return r;
}
__device__ __forceinline__ void upk(ull v, float& x, float& y) {
    asm("mov.b64 {%0, %1}, %2;" : "=f"(x), "=f"(y) : "l"(v));
}
__device__ __forceinline__ void ffma2(ull& d, ull a, ull b) {
    asm("fma.rn.f32x2 %0, %1, %2, %0;" : "+l"(d) : "l"(a), "l"(b));
}

// JAX threefry2x32 (20 rounds)
__device__ __forceinline__ uint2 tf2x32(unsigned k0, unsigned k1, unsigned x0, unsigned x1) {
    unsigned ks2 = k0 ^ k1 ^ 0x1BD11BDAu;
    x0 += k0; x1 += k1;
#define TFR(r) { x0 += x1; x1 = __funnelshift_l(x1, x1, r); x1 ^= x0; }
    TFR(13) TFR(15) TFR(26) TFR(6);  x0 += k1;  x1 += ks2 + 1u;
    TFR(17) TFR(29) TFR(16) TFR(24); x0 += ks2; x1 += k0 + 2u;
    TFR(13) TFR(15) TFR(26) TFR(6);  x0 += k0;  x1 += k1 + 3u;
    TFR(17) TFR(29) TFR(16) TFR(24); x0 += k1;  x1 += ks2 + 4u;
    TFR(13) TFR(15) TFR(26) TFR(6);  x0 += ks2; x1 += k0 + 5u;
#undef TFR
    return make_uint2(x0, x1);
}
__device__ __forceinline__ unsigned rbits_p(unsigned k0, unsigned k1, unsigned m) {
    uint2 p = tf2x32(k0, k1, 0u, m);
    return p.x ^ p.y;
}

__global__ void __launch_bounds__(NTHREADS, 1)
net_kernel(const float* __restrict__ Wih0, const float* __restrict__ Whh0,
           const float* __restrict__ b0,   const float* __restrict__ Wih1,
           const float* __restrict__ Whh1, const float* __restrict__ b1,
           const float* __restrict__ gamma,const float* __restrict__ beta,
           const float* __restrict__ Wout, const float* __restrict__ bout,
           const float* __restrict__ h0in, const float* __restrict__ c0in,
           float* __restrict__ out)
{
    __shared__ float grow[4 * HDIM];
    __shared__ unsigned relay;

    const int tid  = threadIdx.x;
    const int blk  = blockIdx.x;
    const int wid  = tid >> 5;
    const int lane = tid & 31;
    const bool isL0 = (wid < 4);
    const int w    = wid & 3;
    const int col  = blk * 4 + w;

    if (tid == 0) relay = 0u;

    // ---- register-resident weights ----
    // L0 warps: rows 0..3 = Whh0 gates (i,f,g,o) of column col
    // L1 warps: rows 0..3 = Wih1 gates, rows 4..7 = Whh1 gates
    ull wreg[8][4][2];
    {
        const float4* srcA = (const float4*)(isL0 ? Whh0 : Wih1);
#pragma unroll
        for (int r = 0; r < 4; r++) {
            int gr = (r << 9) + col;
#pragma unroll
            for (int c = 0; c < 4; c++) {
                float4 v = srcA[gr * 128 + c * 32 + lane];
                wreg[r][c][0] = pk(v.x, v.y);
                wreg[r][c][1] = pk(v.z, v.w);
            }
        }
        if (!isL0) {
            const float4* srcB = (const float4*)Whh1;
#pragma unroll
            for (int r = 0; r < 4; r++) {
                int gr = (r << 9) + col;
#pragma unroll
                for (int c = 0; c < 4; c++) {
                    float4 v = srcB[gr * 128 + c * 32 + lane];
                    wreg[4 + r][c][0] = pk(v.x, v.y);
                    wreg[4 + r][c][1] = pk(v.z, v.w);
                }
            }
        } else {
#pragma unroll
            for (int r = 4; r < 8; r++)
#pragma unroll
                for (int c = 0; c < 4; c++) { wreg[r][c][0] = 0; wreg[r][c][1] = 0; }
        }
    }

    float biasr = 0.0f;
    if (lane < 4) {
        int gr = (lane << 9) + col;
        if (isL0) {
            float s = 0.0f;
            for (int k = 0; k < 64; k++) s += Wih0[gr * 64 + k];   // x == ones
            biasr = s + b0[gr];
        } else {
            biasr = b1[gr];
        }
    }

    float cst = 0.0f;
    if (lane == 0) cst = isL0 ? c0in[col] : c0in[HDIM + col];
    float bnsum = 0.0f, bnssq = 0.0f;

    // slot-0 carry-in
    if (tid < 4)       __stcg(&g_h0[blk * 4 + tid], h0in[blk * 4 + tid]);
    else if (tid < 8)  __stcg(&g_h1[blk * 4 + tid - 4], h0in[HDIM + blk * 4 + tid - 4]);

    unsigned bar = 0;

    // ---- per-CTA spread-flag barrier: relaxed store arrival, warp0 polls, smem relay ----
#define CTA_BARRIER()                                                            \
    do {                                                                         \
        bar++;                                                                   \
        __syncthreads();                                                         \
        if (wid == 0) {                                                          \
            unsigned* slotp = g_flags + ((bar & 1u) << 7);                       \
            if (lane == 0) { fence_gpu(); st_relaxed_gpu(slotp + blk, bar); }    \
            const uint4* fb = (const uint4*)slotp;                               \
            for (;;) {                                                           \
                uint4 a = ld_vol_v4(fb + lane);                                  \
                bool ok = (a.x == bar) & (a.y == bar) & (a.z == bar) & (a.w == bar); \
                if (__all_sync(0xffffffffu, ok)) break;                          \
            }                                                                    \
            fence_gpu();                                                         \
            if (lane == 0) st_release_cta(&relay, bar);                          \
        } else if (lane == 0) {                                                  \
            while (ld_acquire_cta(&relay) != bar) { }                            \
        }                                                                        \
        __syncwarp();                                                            \
    } while (0)

    CTA_BARRIER();   // publish carry-in

    for (int iter = 0; iter < TSTEPS; ++iter) {
        // ---- recurrence: L1 (warps 4-7) one step behind L0 (warps 0-3) ----
        for (int k = 0; k <= BSEQ; ++k) {
            const bool active = isL0 ? (k < BSEQ) : (k >= 1);
            if (active) {
                const float4* h0p = (const float4*)(g_h0 + (size_t)k * HDIM);
                ull accA[4] = {0, 0, 0, 0}, accB[4] = {0, 0, 0, 0};
#pragma unroll
                for (int c = 0; c < 4; c++) {
                    float4 a = __ldcg(&h0p[c * 32 + lane]);
                    ull a01 = pk(a.x, a.y), a23 = pk(a.z, a.w);
#pragma unroll
                    for (int r = 0; r < 4; r++) {
                        ffma2(accA[r], wreg[r][c][0], a01);
                        ffma2(accB[r], wreg[r][c][1], a23);
                    }
                }
                if (!isL0) {
                    const float4* h1p = (const float4*)(g_h1 + (size_t)(k - 1) * HDIM);
#pragma unroll
                    for (int c = 0; c < 4; c++) {
                        float4 b = __ldcg(&h1p[c * 32 + lane]);
                        ull b01 = pk(b.x, b.y), b23 = pk(b.z, b.w);
#pragma unroll
                        for (int r = 0; r < 4; r++) {
                            ffma2(accA[r], wreg[4 + r][c][0], b01);
                            ffma2(accB[r], wreg[4 + r][c][1], b23);
                        }
                    }
                }
                float s[4];
#pragma unroll
                for (int r = 0; r < 4; r++) {
                    float x0, x1, y0, y1;
                    upk(accA[r], x0, x1); upk(accB[r], y0, y1);
                    s[r] = (x0 + x1) + (y0 + y1);
                }
#pragma unroll
                for (int off = 16; off > 0; off >>= 1) {
#pragma unroll
                    for (int r = 0; r < 4; r++) s[r] += __shfl_xor_sync(0xffffffffu, s[r], off);
                }
                float pre = s[0];
                if (lane == 1) pre = s[1];
                else if (lane == 2) pre = s[2];
                else if (lane == 3) pre = s[3];
                pre += biasr;
                float act = (lane == 2) ? tanh_f(pre) : sigm_f(pre);
                float gi = __shfl_sync(0xffffffffu, act, 0);
                float gf = __shfl_sync(0xffffffffu, act, 1);
                float gg = __shfl_sync(0xffffffffu, act, 2);
                float go = __shfl_sync(0xffffffffu, act, 3);
                if (lane == 0) {
                    cst = gf * cst + gi * gg;
                    float hv = go * tanh_f(cst);
                    if (isL0) {
                        __stcg(&g_h0[(size_t)(k + 1) * HDIM + col], hv);
                        if (k == BSEQ - 1) __stcg(&g_h0[col], hv);   // carry to slot 0
                    } else {
                        __stcg(&g_h1[(size_t)k * HDIM + col], hv);
                        if (k == BSEQ) __stcg(&g_h1[col], hv);       // carry to slot 0
                        bnsum += hv; bnssq += hv * hv;
                    }
                }
            }
            CTA_BARRIER();
        }

        // ---- batchnorm scale/shift ----
        if (!isL0 && lane == 0) {
            float mu  = bnsum * (1.0f / 512.0f);
            float var = bnssq * (1.0f / 512.0f) - mu * mu;
            float inv = 1.0f / sqrtf(var + 1e-5f);
            float sc  = gamma[col] * inv;
            __stcg(&g_scale[col], sc);
            __stcg(&g_shift[col], beta[col] - mu * sc);
            bnsum = 0.0f; bnssq = 0.0f;
        }
        CTA_BARRIER();

        // ---- BN + gaussian + logits + threefry categorical (L0 warps only) ----
        if (isL0) {
            int b = blk * 4 + w;
            float* gr = grow + w * HDIM;
            const float* yrow = g_h1 + (size_t)(b + 1) * HDIM;
#pragma unroll
            for (int c = 0; c < 16; c++) {
                int cc = c * 32 + lane;
                float v  = __ldcg(&yrow[cc]);
                float yn = v * __ldcg(&g_scale[cc]) + __ldcg(&g_shift[cc]);
                gr[cc] = expf(-yn * yn);
            }
            __syncwarp();

            float logit = -CUDART_INF_F;
            if (lane < OUTC) {
                float acc = bout[lane];
                const float* wrow = Wout + lane * HDIM;
#pragma unroll 8
                for (int k = 0; k < HDIM; k++) acc += gr[k] * __ldg(wrow + k);
                logit = acc;
            }

            uint2 kp = tf2x32(0u, 42u, 0u, (unsigned)iter);
            bool full = (iter < 15);

            float v = -CUDART_INF_F;
            int idx = lane;
            bool cand = full ? (lane < 12) : (lane >= 8 && lane < 12);
            if (cand) {
                unsigned m = full ? (unsigned)(b * 12 + lane) : (unsigned)(b * 4 + (lane - 8));
                unsigned bits = rbits_p(kp.x, kp.y, m);
                float u = __uint_as_float((bits >> 9) | 0x3f800000u) - 1.0f;
                u = fmaxf(u, 1.17549435e-38f);
                v = -logf(-logf(u)) + logit;
            }
#pragma unroll
            for (int off = 16; off > 0; off >>= 1) {
                float ov = __shfl_xor_sync(0xffffffffu, v, off);
                int   oi = __shfl_xor_sync(0xffffffffu, idx, off);
                if (ov > v || (ov == v && oi < idx)) { v = ov; idx = oi; }
            }
            float lm = logit;
#pragma unroll
            for (int off = 16; off > 0; off >>= 1) lm = fmaxf(lm, __shfl_xor_sync(0xffffffffu, lm, off));
            float e = (lane < OUTC) ? expf(logit - lm) : 0.0f;
#pragma unroll
            for (int off = 16; off > 0; off >>= 1) e += __shfl_xor_sync(0xffffffffu, e, off);
            float la = __shfl_sync(0xffffffffu, logit, idx);
            float lp = la - lm - logf(e);

            if (lane == 0) {
                out[iter * BSEQ + b]                 = (float)idx;
                out[TSTEPS * BSEQ + iter * BSEQ + b] = lp;
            }
        }
        // next iteration's first barrier protects g_h1 / scale / shift reuse
    }
}

extern "C" void kernel_launch(void* const* d_in, const int* in_sizes, int n_in,
                              void* d_out, int out_size) {
    (void)in_sizes; (void)n_in; (void)out_size;
    const float* Wih0  = (const float*)d_in[0];
    const float* Whh0  = (const float*)d_in[1];
    const float* b0    = (const float*)d_in[2];
    const float* Wih1  = (const float*)d_in[3];
    const float* Whh1  = (const float*)d_in[4];
    const float* b1    = (const float*)d_in[5];
    const float* gamma = (const float*)d_in[6];
    const float* beta  = (const float*)d_in[7];
    const float* Wout  = (const float*)d_in[8];
    const float* bout  = (const float*)d_in[9];
    const float* h0in  = (const float*)d_in[10];
    const float* c0in  = (const float*)d_in[11];
    float* out = (float*)d_out;

    net_kernel<<<NCTA, NTHREADS>>>(Wih0, Whh0, b0, Wih1, Whh1, b1,
                                   gamma, beta, Wout, bout, h0in, c0in, out);
}

// round 11
// speedup vs baseline: 1.5282x; 1.5282x over previous
#include <cuda_runtime.h>
#include <cstdint>
#include <math.h>
#include <math_constants.h>

#define NCTA     128
#define NTHREADS 256
#define HDIM     512
#define TSTEPS   31
#define BSEQ     512
#define OUTC     12
#define NCNT     16

typedef unsigned long long ull;

// ---------------- device globals (scratch) ----------------
__device__ float g_h0[(BSEQ + 1) * HDIM];
__device__ float g_h1[(BSEQ + 1) * HDIM];
__device__ float g_scale[HDIM];
__device__ float g_shift[HDIM];
// 16 monotonic arrival counters, 128B apart (distinct L2 lines)
__device__ unsigned g_cnt[NCNT * 32];

__device__ __forceinline__ void red_add_release(unsigned* p, unsigned v) {
    asm volatile("red.release.gpu.global.add.u32 [%0], %1;" :: "l"(p), "r"(v) : "memory");
}
__device__ __forceinline__ unsigned ld_acquire_gpu(const unsigned* p) {
    unsigned v;
    asm volatile("ld.acquire.gpu.global.u32 %0, [%1];" : "=r"(v) : "l"(p) : "memory");
    return v;
}

// fast activations (rel err ~1e-6)
__device__ __forceinline__ float sigm_f(float x) { return __fdividef(1.0f, 1.0f + __expf(-x)); }
__device__ __forceinline__ float tanh_f(float x) { return 1.0f - __fdividef(2.0f, __expf(2.0f * x) + 1.0f); }

// packed fp32x2 (sm_103a FFMA2 via PTX)
__device__ __forceinline__ ull pk(float x, float y) {
    ull r; asm("mov.b64 %0, {%1, %2};" : "=l"(r) : "f"(x), "f"(y)); return r;
}
__device__ __forceinline__ void upk(ull v, float& x, float& y) {
    asm("mov.b64 {%0, %1}, %2;" : "=f"(x), "=f"(y) : "l"(v));
}
__device__ __forceinline__ void ffma2(ull& d, ull a, ull b) {
    asm("fma.rn.f32x2 %0, %1, %2, %0;" : "+l"(d) : "l"(a), "l"(b));
}

// JAX threefry2x32 (20 rounds)
__device__ __forceinline__ uint2 tf2x32(unsigned k0, unsigned k1, unsigned x0, unsigned x1) {
    unsigned ks2 = k0 ^ k1 ^ 0x1BD11BDAu;
    x0 += k0; x1 += k1;
#define TFR(r) { x0 += x1; x1 = __funnelshift_l(x1, x1, r); x1 ^= x0; }
    TFR(13) TFR(15) TFR(26) TFR(6);  x0 += k1;  x1 += ks2 + 1u;
    TFR(17) TFR(29) TFR(16) TFR(24); x0 += ks2; x1 += k0 + 2u;
    TFR(13) TFR(15) TFR(26) TFR(6);  x0 += k0;  x1 += k1 + 3u;
    TFR(17) TFR(29) TFR(16) TFR(24); x0 += k1;  x1 += ks2 + 4u;
    TFR(13) TFR(15) TFR(26) TFR(6);  x0 += ks2; x1 += k0 + 5u;
#undef TFR
    return make_uint2(x0, x1);
}
__device__ __forceinline__ unsigned rbits_p(unsigned k0, unsigned k1, unsigned m) {
    uint2 p = tf2x32(k0, k1, 0u, m);
    return p.x ^ p.y;
}

// zero the barrier counters before every run (graph-replay safety)
__global__ void zero_kernel() {
    if (threadIdx.x < NCNT * 32) g_cnt[threadIdx.x] = 0u;
}

__global__ void __launch_bounds__(NTHREADS, 1)
net_kernel(const float* __restrict__ Wih0, const float* __restrict__ Whh0,
           const float* __restrict__ b0,   const float* __restrict__ Wih1,
           const float* __restrict__ Whh1, const float* __restrict__ b1,
           const float* __restrict__ gamma,const float* __restrict__ beta,
           const float* __restrict__ Wout, const float* __restrict__ bout,
           const float* __restrict__ h0in, const float* __restrict__ c0in,
           float* __restrict__ out)
{
    __shared__ float grow[4 * HDIM];

    const int tid  = threadIdx.x;
    const int blk  = blockIdx.x;
    const int wid  = tid >> 5;
    const int lane = tid & 31;
    const bool isL0 = (wid < 4);
    const int w    = wid & 3;
    const int col  = blk * 4 + w;
    const int mycnt = (blk & (NCNT - 1)) * 32;

    // ---- register-resident weights ----
    // L0 warps: rows 0..3 = Whh0 gates (i,f,g,o) of column col
    // L1 warps: rows 0..3 = Wih1 gates, rows 4..7 = Whh1 gates
    ull wreg[8][4][2];
    {
        const float4* srcA = (const float4*)(isL0 ? Whh0 : Wih1);
#pragma unroll
        for (int r = 0; r < 4; r++) {
            int gr = (r << 9) + col;
#pragma unroll
            for (int c = 0; c < 4; c++) {
                float4 v = srcA[gr * 128 + c * 32 + lane];
                wreg[r][c][0] = pk(v.x, v.y);
                wreg[r][c][1] = pk(v.z, v.w);
            }
        }
        if (!isL0) {
            const float4* srcB = (const float4*)Whh1;
#pragma unroll
            for (int r = 0; r < 4; r++) {
                int gr = (r << 9) + col;
#pragma unroll
                for (int c = 0; c < 4; c++) {
                    float4 v = srcB[gr * 128 + c * 32 + lane];
                    wreg[4 + r][c][0] = pk(v.x, v.y);
                    wreg[4 + r][c][1] = pk(v.z, v.w);
                }
            }
        } else {
#pragma unroll
            for (int r = 4; r < 8; r++)
#pragma unroll
                for (int c = 0; c < 4; c++) { wreg[r][c][0] = 0; wreg[r][c][1] = 0; }
        }
    }

    float biasr = 0.0f;
    if (lane < 4) {
        int gr = (lane << 9) + col;
        if (isL0) {
            float s = 0.0f;
            for (int k = 0; k < 64; k++) s += Wih0[gr * 64 + k];   // x == ones
            biasr = s + b0[gr];
        } else {
            biasr = b1[gr];
        }
    }

    float cst = 0.0f;
    if (lane == 0) cst = isL0 ? c0in[col] : c0in[HDIM + col];
    float bnsum = 0.0f, bnssq = 0.0f;

    // slot-0 carry-in
    if (tid < 4)       __stcg(&g_h0[blk * 4 + tid], h0in[blk * 4 + tid]);
    else if (tid < 8)  __stcg(&g_h1[blk * 4 + tid - 4], h0in[HDIM + blk * 4 + tid - 4]);

    unsigned bar = 0;

    // ---- spread-atomic monotonic barrier: red to 1-of-16 counters, all-warp value spin ----
#define SPREAD_BARRIER()                                                         \
    do {                                                                         \
        bar++;                                                                   \
        __syncthreads();                                                         \
        if (tid == 0) { __threadfence(); red_add_release(&g_cnt[mycnt], 1u); }   \
        const unsigned tgt = bar * (NCTA / NCNT);                                \
        for (;;) {                                                               \
            unsigned c = tgt;                                                    \
            if (lane < NCNT) c = ld_acquire_gpu(&g_cnt[lane * 32]);              \
            if (__all_sync(0xffffffffu, c >= tgt)) break;                        \
        }                                                                        \
    } while (0)

    SPREAD_BARRIER();   // publish carry-in

    for (int iter = 0; iter < TSTEPS; ++iter) {
        // ---- recurrence: L1 (warps 4-7) one step behind L0 (warps 0-3) ----
        for (int k = 0; k <= BSEQ; ++k) {
            const bool active = isL0 ? (k < BSEQ) : (k >= 1);
            if (active) {
                const float4* h0p = (const float4*)(g_h0 + (size_t)k * HDIM);
                ull accA[4] = {0, 0, 0, 0}, accB[4] = {0, 0, 0, 0};
#pragma unroll
                for (int c = 0; c < 4; c++) {
                    float4 a = __ldcg(&h0p[c * 32 + lane]);
                    ull a01 = pk(a.x, a.y), a23 = pk(a.z, a.w);
#pragma unroll
                    for (int r = 0; r < 4; r++) {
                        ffma2(accA[r], wreg[r][c][0], a01);
                        ffma2(accB[r], wreg[r][c][1], a23);
                    }
                }
                if (!isL0) {
                    const float4* h1p = (const float4*)(g_h1 + (size_t)(k - 1) * HDIM);
#pragma unroll
                    for (int c = 0; c < 4; c++) {
                        float4 b = __ldcg(&h1p[c * 32 + lane]);
                        ull b01 = pk(b.x, b.y), b23 = pk(b.z, b.w);
#pragma unroll
                        for (int r = 0; r < 4; r++) {
                            ffma2(accA[r], wreg[4 + r][c][0], b01);
                            ffma2(accB[r], wreg[4 + r][c][1], b23);
                        }
                    }
                }
                float s[4];
#pragma unroll
                for (int r = 0; r < 4; r++) {
                    float x0, x1, y0, y1;
                    upk(accA[r], x0, x1); upk(accB[r], y0, y1);
                    s[r] = (x0 + x1) + (y0 + y1);
                }
#pragma unroll
                for (int off = 16; off > 0; off >>= 1) {
#pragma unroll
                    for (int r = 0; r < 4; r++) s[r] += __shfl_xor_sync(0xffffffffu, s[r], off);
                }
                float pre = s[0];
                if (lane == 1) pre = s[1];
                else if (lane == 2) pre = s[2];
                else if (lane == 3) pre = s[3];
                pre += biasr;
                float act = (lane == 2) ? tanh_f(pre) : sigm_f(pre);
                float gi = __shfl_sync(0xffffffffu, act, 0);
                float gf = __shfl_sync(0xffffffffu, act, 1);
                float gg = __shfl_sync(0xffffffffu, act, 2);
                float go = __shfl_sync(0xffffffffu, act, 3);
                if (lane == 0) {
                    cst = gf * cst + gi * gg;
                    float hv = go * tanh_f(cst);
                    if (isL0) {
                        __stcg(&g_h0[(size_t)(k + 1) * HDIM + col], hv);
                        if (k == BSEQ - 1) __stcg(&g_h0[col], hv);   // carry to slot 0
                    } else {
                        __stcg(&g_h1[(size_t)k * HDIM + col], hv);
                        if (k == BSEQ) __stcg(&g_h1[col], hv);       // carry to slot 0
                        bnsum += hv; bnssq += hv * hv;
                    }
                }
            }
            SPREAD_BARRIER();
        }

        // ---- batchnorm scale/shift ----
        if (!isL0 && lane == 0) {
            float mu  = bnsum * (1.0f / 512.0f);
            float var = bnssq * (1.0f / 512.0f) - mu * mu;
            float inv = 1.0f / sqrtf(var + 1e-5f);
            float sc  = gamma[col] * inv;
            __stcg(&g_scale[col], sc);
            __stcg(&g_shift[col], beta[col] - mu * sc);
            bnsum = 0.0f; bnssq = 0.0f;
        }
        SPREAD_BARRIER();

        // ---- BN + gaussian + logits + threefry categorical (L0 warps only) ----
        if (isL0) {
            int b = blk * 4 + w;
            float* gr = grow + w * HDIM;
            const float* yrow = g_h1 + (size_t)(b + 1) * HDIM;
#pragma unroll
            for (int c = 0; c < 16; c++) {
                int cc = c * 32 + lane;
                float v  = __ldcg(&yrow[cc]);
                float yn = v * __ldcg(&g_scale[cc]) + __ldcg(&g_shift[cc]);
                gr[cc] = expf(-yn * yn);
            }
            __syncwarp();

            float logit = -CUDART_INF_F;
            if (lane < OUTC) {
                float acc = bout[lane];
                const float* wrow = Wout + lane * HDIM;
#pragma unroll 8
                for (int k = 0; k < HDIM; k++) acc += gr[k] * __ldg(wrow + k);
                logit = acc;
            }

            uint2 kp = tf2x32(0u, 42u, 0u, (unsigned)iter);
            bool full = (iter < 15);

            float v = -CUDART_INF_F;
            int idx = lane;
            bool cand = full ? (lane < 12) : (lane >= 8 && lane < 12);
            if (cand) {
                unsigned m = full ? (unsigned)(b * 12 + lane) : (unsigned)(b * 4 + (lane - 8));
                unsigned bits = rbits_p(kp.x, kp.y, m);
                float u = __uint_as_float((bits >> 9) | 0x3f800000u) - 1.0f;
                u = fmaxf(u, 1.17549435e-38f);
                v = -logf(-logf(u)) + logit;
            }
#pragma unroll
            for (int off = 16; off > 0; off >>= 1) {
                float ov = __shfl_xor_sync(0xffffffffu, v, off);
                int   oi = __shfl_xor_sync(0xffffffffu, idx, off);
                if (ov > v || (ov == v && oi < idx)) { v = ov; idx = oi; }
            }
            float lm = logit;
#pragma unroll
            for (int off = 16; off > 0; off >>= 1) lm = fmaxf(lm, __shfl_xor_sync(0xffffffffu, lm, off));
            float e = (lane < OUTC) ? expf(logit - lm) : 0.0f;
#pragma unroll
            for (int off = 16; off > 0; off >>= 1) e += __shfl_xor_sync(0xffffffffu, e, off);
            float la = __shfl_sync(0xffffffffu, logit, idx);
            float lp = la - lm - logf(e);

            if (lane == 0) {
                out[iter * BSEQ + b]                 = (float)idx;
                out[TSTEPS * BSEQ + iter * BSEQ + b] = lp;
            }
        }
        // next iteration's first barrier protects g_h1 / scale / shift reuse
    }
}

extern "C" void kernel_launch(void* const* d_in, const int* in_sizes, int n_in,
                              void* d_out, int out_size) {
    (void)in_sizes; (void)n_in; (void)out_size;
    const float* Wih0  = (const float*)d_in[0];
    const float* Whh0  = (const float*)d_in[1];
    const float* b0    = (const float*)d_in[2];
    const float* Wih1  = (const float*)d_in[3];
    const float* Whh1  = (const float*)d_in[4];
    const float* b1    = (const float*)d_in[5];
    const float* gamma = (const float*)d_in[6];
    const float* beta  = (const float*)d_in[7];
    const float* Wout  = (const float*)d_in[8];
    const float* bout  = (const float*)d_in[9];
    const float* h0in  = (const float*)d_in[10];
    const float* c0in  = (const float*)d_in[11];
    float* out = (float*)d_out;

    zero_kernel<<<1, 512>>>();
    net_kernel<<<NCTA, NTHREADS>>>(Wih0, Whh0, b0, Wih1, Whh1, b1,
                                   gamma, beta, Wout, bout, h0in, c0in, out);
}

// round 12
// speedup vs baseline: 2.7173x; 1.7781x over previous
#include <cuda_runtime.h>
#include <cstdint>
#include <math.h>
#include <math_constants.h>

#define NCTA     128
#define NTHREADS 256
#define HDIM     512
#define TSTEPS   31
#define BSEQ     512
#define OUTC     12
#define NGROUP   16
#define GSIZE    8

typedef unsigned long long ull;

// ---------------- device globals (scratch) ----------------
__device__ float g_h0[(BSEQ + 1) * HDIM];
__device__ float g_h1[(BSEQ + 1) * HDIM];
__device__ float g_scale[HDIM];
__device__ float g_shift[HDIM];
// monotonic two-level barrier state; each word on its own 128B line
__device__ unsigned g_gcnt[NGROUP * 32];
__device__ unsigned g_root[32];
__device__ unsigned g_gen[32];

__device__ __forceinline__ unsigned ld_acquire_gpu(const unsigned* p) {
    unsigned v;
    asm volatile("ld.acquire.gpu.global.u32 %0, [%1];" : "=r"(v) : "l"(p) : "memory");
    return v;
}
__device__ __forceinline__ void st_release_gpu(unsigned* p, unsigned v) {
    asm volatile("st.release.gpu.global.u32 [%0], %1;" :: "l"(p), "r"(v) : "memory");
}

// fast activations (rel err ~1e-6)
__device__ __forceinline__ float sigm_f(float x) { return __fdividef(1.0f, 1.0f + __expf(-x)); }
__device__ __forceinline__ float tanh_f(float x) { return 1.0f - __fdividef(2.0f, __expf(2.0f * x) + 1.0f); }

// packed fp32x2 (sm_103a FFMA2 via PTX)
__device__ __forceinline__ ull pk(float x, float y) {
    ull r; asm("mov.b64 %0, {%1, %2};" : "=l"(r) : "f"(x), "f"(y)); return r;
}
__device__ __forceinline__ void upk(ull v, float& x, float& y) {
    asm("mov.b64 {%0, %1}, %2;" : "=f"(x), "=f"(y) : "l"(v));
}
__device__ __forceinline__ void ffma2(ull& d, ull a, ull b) {
    asm("fma.rn.f32x2 %0, %1, %2, %0;" : "+l"(d) : "l"(a), "l"(b));
}

// JAX threefry2x32 (20 rounds)
__device__ __forceinline__ uint2 tf2x32(unsigned k0, unsigned k1, unsigned x0, unsigned x1) {
    unsigned ks2 = k0 ^ k1 ^ 0x1BD11BDAu;
    x0 += k0; x1 += k1;
#define TFR(r) { x0 += x1; x1 = __funnelshift_l(x1, x1, r); x1 ^= x0; }
    TFR(13) TFR(15) TFR(26) TFR(6);  x0 += k1;  x1 += ks2 + 1u;
    TFR(17) TFR(29) TFR(16) TFR(24); x0 += ks2; x1 += k0 + 2u;
    TFR(13) TFR(15) TFR(26) TFR(6);  x0 += k0;  x1 += k1 + 3u;
    TFR(17) TFR(29) TFR(16) TFR(24); x0 += k1;  x1 += ks2 + 4u;
    TFR(13) TFR(15) TFR(26) TFR(6);  x0 += ks2; x1 += k0 + 5u;
#undef TFR
    return make_uint2(x0, x1);
}
__device__ __forceinline__ unsigned rbits_p(unsigned k0, unsigned k1, unsigned m) {
    uint2 p = tf2x32(k0, k1, 0u, m);
    return p.x ^ p.y;
}

// reset monotonic barrier state every run (graph-replay safety)
__global__ void zero_kernel() {
    int i = threadIdx.x;
    if (i < NGROUP * 32) g_gcnt[i] = 0u;
    if (i < 32) { g_root[i] = 0u; g_gen[i] = 0u; }
}

__global__ void __launch_bounds__(NTHREADS, 1)
net_kernel(const float* __restrict__ Wih0, const float* __restrict__ Whh0,
           const float* __restrict__ b0,   const float* __restrict__ Wih1,
           const float* __restrict__ Whh1, const float* __restrict__ b1,
           const float* __restrict__ gamma,const float* __restrict__ beta,
           const float* __restrict__ Wout, const float* __restrict__ bout,
           const float* __restrict__ h0in, const float* __restrict__ c0in,
           float* __restrict__ out)
{
    __shared__ float grow[4 * HDIM];

    const int tid  = threadIdx.x;
    const int blk  = blockIdx.x;
    const int wid  = tid >> 5;
    const int lane = tid & 31;
    const bool isL0 = (wid < 4);
    const int w    = wid & 3;
    const int col  = blk * 4 + w;
    const int grp  = blk & (NGROUP - 1);

    // ---- register-resident weights ----
    // L0 warps: rows 0..3 = Whh0 gates (i,f,g,o) of column col
    // L1 warps: rows 0..3 = Wih1 gates, rows 4..7 = Whh1 gates
    ull wreg[8][4][2];
    {
        const float4* srcA = (const float4*)(isL0 ? Whh0 : Wih1);
#pragma unroll
        for (int r = 0; r < 4; r++) {
            int gr = (r << 9) + col;
#pragma unroll
            for (int c = 0; c < 4; c++) {
                float4 v = srcA[gr * 128 + c * 32 + lane];
                wreg[r][c][0] = pk(v.x, v.y);
                wreg[r][c][1] = pk(v.z, v.w);
            }
        }
        if (!isL0) {
            const float4* srcB = (const float4*)Whh1;
#pragma unroll
            for (int r = 0; r < 4; r++) {
                int gr = (r << 9) + col;
#pragma unroll
                for (int c = 0; c < 4; c++) {
                    float4 v = srcB[gr * 128 + c * 32 + lane];
                    wreg[4 + r][c][0] = pk(v.x, v.y);
                    wreg[4 + r][c][1] = pk(v.z, v.w);
                }
            }
        } else {
#pragma unroll
            for (int r = 4; r < 8; r++)
#pragma unroll
                for (int c = 0; c < 4; c++) { wreg[r][c][0] = 0; wreg[r][c][1] = 0; }
        }
    }

    float biasr = 0.0f;
    if (lane < 4) {
        int gr = (lane << 9) + col;
        if (isL0) {
            float s = 0.0f;
            for (int k = 0; k < 64; k++) s += Wih0[gr * 64 + k];   // x == ones
            biasr = s + b0[gr];
        } else {
            biasr = b1[gr];
        }
    }

    float cst = 0.0f;
    if (lane == 0) cst = isL0 ? c0in[col] : c0in[HDIM + col];
    float bnsum = 0.0f, bnssq = 0.0f;

    // slot-0 carry-in
    if (tid < 4)       __stcg(&g_h0[blk * 4 + tid], h0in[blk * 4 + tid]);
    else if (tid < 8)  __stcg(&g_h1[blk * 4 + tid - 4], h0in[HDIM + blk * 4 + tid - 4]);

    unsigned bar = 0;

    // ---- two-level atomic barrier, R5 shape: only tid0 touches L2, all else at BAR ----
#define TL_BARRIER()                                                              \
    do {                                                                          \
        bar++;                                                                    \
        __syncthreads();                                                          \
        if (tid == 0) {                                                           \
            __threadfence();                                                      \
            unsigned o = atomicAdd(&g_gcnt[grp * 32], 1u);                        \
            if (o == bar * GSIZE - 1u) {                                          \
                unsigned o2 = atomicAdd(&g_root[0], 1u);                          \
                if (o2 == bar * NGROUP - 1u) st_release_gpu(&g_gen[0], bar);      \
            }                                                                     \
            while (ld_acquire_gpu(&g_gen[0]) < bar) { }                           \
        }                                                                         \
        __syncthreads();                                                          \
    } while (0)

    TL_BARRIER();   // publish carry-in

    for (int iter = 0; iter < TSTEPS; ++iter) {
        // ---- recurrence: L1 (warps 4-7) one step behind L0 (warps 0-3) ----
        for (int k = 0; k <= BSEQ; ++k) {
            const bool active = isL0 ? (k < BSEQ) : (k >= 1);
            if (active) {
                const float4* h0p = (const float4*)(g_h0 + (size_t)k * HDIM);
                ull accA[4] = {0, 0, 0, 0}, accB[4] = {0, 0, 0, 0};
#pragma unroll
                for (int c = 0; c < 4; c++) {
                    float4 a = __ldcg(&h0p[c * 32 + lane]);
                    ull a01 = pk(a.x, a.y), a23 = pk(a.z, a.w);
#pragma unroll
                    for (int r = 0; r < 4; r++) {
                        ffma2(accA[r], wreg[r][c][0], a01);
                        ffma2(accB[r], wreg[r][c][1], a23);
                    }
                }
                if (!isL0) {
                    const float4* h1p = (const float4*)(g_h1 + (size_t)(k - 1) * HDIM);
#pragma unroll
                    for (int c = 0; c < 4; c++) {
                        float4 b = __ldcg(&h1p[c * 32 + lane]);
                        ull b01 = pk(b.x, b.y), b23 = pk(b.z, b.w);
#pragma unroll
                        for (int r = 0; r < 4; r++) {
                            ffma2(accA[r], wreg[4 + r][c][0], b01);
                            ffma2(accB[r], wreg[4 + r][c][1], b23);
                        }
                    }
                }
                float s[4];
#pragma unroll
                for (int r = 0; r < 4; r++) {
                    float x0, x1, y0, y1;
                    upk(accA[r], x0, x1); upk(accB[r], y0, y1);
                    s[r] = (x0 + x1) + (y0 + y1);
                }
#pragma unroll
                for (int off = 16; off > 0; off >>= 1) {
#pragma unroll
                    for (int r = 0; r < 4; r++) s[r] += __shfl_xor_sync(0xffffffffu, s[r], off);
                }
                float pre = s[0];
                if (lane == 1) pre = s[1];
                else if (lane == 2) pre = s[2];
                else if (lane == 3) pre = s[3];
                pre += biasr;
                float act = (lane == 2) ? tanh_f(pre) : sigm_f(pre);
                float gi = __shfl_sync(0xffffffffu, act, 0);
                float gf = __shfl_sync(0xffffffffu, act, 1);
                float gg = __shfl_sync(0xffffffffu, act, 2);
                float go = __shfl_sync(0xffffffffu, act, 3);
                if (lane == 0) {
                    cst = gf * cst + gi * gg;
                    float hv = go * tanh_f(cst);
                    if (isL0) {
                        __stcg(&g_h0[(size_t)(k + 1) * HDIM + col], hv);
                        if (k == BSEQ - 1) __stcg(&g_h0[col], hv);   // carry to slot 0
                    } else {
                        __stcg(&g_h1[(size_t)k * HDIM + col], hv);
                        bnsum += hv; bnssq += hv * hv;
                        if (k == BSEQ) {
                            __stcg(&g_h1[col], hv);                  // carry to slot 0
                            // batchnorm scale/shift merged into this round
                            float mu  = bnsum * (1.0f / 512.0f);
                            float var = bnssq * (1.0f / 512.0f) - mu * mu;
                            float inv = 1.0f / sqrtf(var + 1e-5f);
                            float sc  = gamma[col] * inv;
                            __stcg(&g_scale[col], sc);
                            __stcg(&g_shift[col], beta[col] - mu * sc);
                            bnsum = 0.0f; bnssq = 0.0f;
                        }
                    }
                }
            }
            TL_BARRIER();
        }

        // ---- BN + gaussian + logits + threefry categorical (L0 warps only) ----
        // (scale/shift and g_h1 rows were published by the k=512 barrier)
        if (isL0) {
            int b = blk * 4 + w;
            float* gr = grow + w * HDIM;
            const float* yrow = g_h1 + (size_t)(b + 1) * HDIM;
#pragma unroll
            for (int c = 0; c < 16; c++) {
                int cc = c * 32 + lane;
                float v  = __ldcg(&yrow[cc]);
                float yn = v * __ldcg(&g_scale[cc]) + __ldcg(&g_shift[cc]);
                gr[cc] = expf(-yn * yn);
            }
            __syncwarp();

            float logit = -CUDART_INF_F;
            if (lane < OUTC) {
                float acc = bout[lane];
                const float* wrow = Wout + lane * HDIM;
#pragma unroll 8
                for (int k = 0; k < HDIM; k++) acc += gr[k] * __ldg(wrow + k);
                logit = acc;
            }

            uint2 kp = tf2x32(0u, 42u, 0u, (unsigned)iter);
            bool full = (iter < 15);

            float v = -CUDART_INF_F;
            int idx = lane;
            bool cand = full ? (lane < 12) : (lane >= 8 && lane < 12);
            if (cand) {
                unsigned m = full ? (unsigned)(b * 12 + lane) : (unsigned)(b * 4 + (lane - 8));
                unsigned bits = rbits_p(kp.x, kp.y, m);
                float u = __uint_as_float((bits >> 9) | 0x3f800000u) - 1.0f;
                u = fmaxf(u, 1.17549435e-38f);
                v = -logf(-logf(u)) + logit;
            }
#pragma unroll
            for (int off = 16; off > 0; off >>= 1) {
                float ov = __shfl_xor_sync(0xffffffffu, v, off);
                int   oi = __shfl_xor_sync(0xffffffffu, idx, off);
                if (ov > v || (ov == v && oi < idx)) { v = ov; idx = oi; }
            }
            float lm = logit;
#pragma unroll
            for (int off = 16; off > 0; off >>= 1) lm = fmaxf(lm, __shfl_xor_sync(0xffffffffu, lm, off));
            float e = (lane < OUTC) ? expf(logit - lm) : 0.0f;
#pragma unroll
            for (int off = 16; off > 0; off >>= 1) e += __shfl_xor_sync(0xffffffffu, e, off);
            float la = __shfl_sync(0xffffffffu, logit, idx);
            float lp = la - lm - logf(e);

            if (lane == 0) {
                out[iter * BSEQ + b]                 = (float)idx;
                out[TSTEPS * BSEQ + iter * BSEQ + b] = lp;
            }
        }
        // next iteration's k=0 barrier orders phase-3 reads before L1's k=1 writes
    }
}

extern "C" void kernel_launch(void* const* d_in, const int* in_sizes, int n_in,
                              void* d_out, int out_size) {
    (void)in_sizes; (void)n_in; (void)out_size;
    const float* Wih0  = (const float*)d_in[0];
    const float* Whh0  = (const float*)d_in[1];
    const float* b0    = (const float*)d_in[2];
    const float* Wih1  = (const float*)d_in[3];
    const float* Whh1  = (const float*)d_in[4];
    const float* b1    = (const float*)d_in[5];
    const float* gamma = (const float*)d_in[6];
    const float* beta  = (const float*)d_in[7];
    const float* Wout  = (const float*)d_in[8];
    const float* bout  = (const float*)d_in[9];
    const float* h0in  = (const float*)d_in[10];
    const float* c0in  = (const float*)d_in[11];
    float* out = (float*)d_out;

    zero_kernel<<<1, NGROUP * 32>>>();
    net_kernel<<<NCTA, NTHREADS>>>(Wih0, Whh0, b0, Wih1, Whh1, b1,
                                   gamma, beta, Wout, bout, h0in, c0in, out);
}